// round 1
// baseline (speedup 1.0000x reference)
#include <cuda_runtime.h>
#include <math.h>

// Problem constants
#define SEQ   2048
#define DIM   4096
#define NH    32
#define NKV   8
#define HD    128
#define KVDIM 1024   // NKV * HD

// ----------------------------------------------------------------------------
// Scratch (device-global: no allocations allowed anywhere)
// ----------------------------------------------------------------------------
__device__ float  g_Q[SEQ * DIM];      // 33.5 MB
__device__ float  g_K[SEQ * KVDIM];    //  8.4 MB
__device__ float  g_V[SEQ * KVDIM];    //  8.4 MB
__device__ float  g_attn[SEQ * DIM];   // 33.5 MB
__device__ float2 g_cs[SEQ * (HD / 2)];// rope cos/sin table

// ----------------------------------------------------------------------------
// RoPE cos/sin table (double-precision angles to match the fp32 reference
// within tolerance; tiny kernel, recomputed every launch for determinism)
// ----------------------------------------------------------------------------
__global__ void __launch_bounds__(256) rope_table_kernel()
{
    int idx = blockIdx.x * blockDim.x + threadIdx.x;
    if (idx >= SEQ * 64) return;
    int s = idx >> 6, i = idx & 63;
    double freq = exp(-(double)i / 64.0 * log(500000.0));
    double a = (double)s * freq;
    g_cs[idx] = make_float2((float)cos(a), (float)sin(a));
}

// ----------------------------------------------------------------------------
// RoPE apply: pairs (2i, 2i+1) within each head
// ----------------------------------------------------------------------------
__global__ void __launch_bounds__(256) rope_kernel(float* __restrict__ X,
                                                   int nheads, int rowstride)
{
    int idx = blockIdx.x * blockDim.x + threadIdx.x;
    int i  = idx & 63;
    int hs = idx >> 6;          // h + s*nheads
    int h  = hs % nheads;
    int s  = hs / nheads;
    float2 cs = g_cs[(s << 6) + i];
    float2* p = (float2*)(X + (size_t)s * rowstride + h * HD) + i;
    float2 v = *p;
    *p = make_float2(v.x * cs.x - v.y * cs.y,
                     v.x * cs.y + v.y * cs.x);
}

// ----------------------------------------------------------------------------
// C[M,N] = A[M,K] * B[N,K]^T   (both row-major; M,N multiples of 128, K of 8)
// 128x128 block tile, BK=8, 256 threads, 8x8 register micro-tile.
// ----------------------------------------------------------------------------
__global__ void __launch_bounds__(256) gemm128(const float* __restrict__ A,
                                               const float* __restrict__ B,
                                               float* __restrict__ C,
                                               int N, int K)
{
    __shared__ float As[8][128];
    __shared__ float Bs[8][128];
    const int t  = threadIdx.x;
    const int tx = t & 15;
    const int ty = t >> 4;
    const int m0 = blockIdx.y << 7;
    const int n0 = blockIdx.x << 7;
    const int lm = t >> 1;
    const int lk = (t & 1) << 2;

    const float* Ap = A + (size_t)(m0 + lm) * K + lk;
    const float* Bp = B + (size_t)(n0 + lm) * K + lk;

    float acc[8][8];
#pragma unroll
    for (int i = 0; i < 8; i++)
#pragma unroll
        for (int j = 0; j < 8; j++) acc[i][j] = 0.f;

    for (int k0 = 0; k0 < K; k0 += 8) {
        float4 av = *(const float4*)(Ap + k0);
        float4 bv = *(const float4*)(Bp + k0);
        __syncthreads();
        As[lk + 0][lm] = av.x; As[lk + 1][lm] = av.y;
        As[lk + 2][lm] = av.z; As[lk + 3][lm] = av.w;
        Bs[lk + 0][lm] = bv.x; Bs[lk + 1][lm] = bv.y;
        Bs[lk + 2][lm] = bv.z; Bs[lk + 3][lm] = bv.w;
        __syncthreads();
#pragma unroll
        for (int kk = 0; kk < 8; kk++) {
            float a[8], b[8];
            *(float4*)(a)     = *(const float4*)&As[kk][ty * 8];
            *(float4*)(a + 4) = *(const float4*)&As[kk][ty * 8 + 4];
            *(float4*)(b)     = *(const float4*)&Bs[kk][tx * 8];
            *(float4*)(b + 4) = *(const float4*)&Bs[kk][tx * 8 + 4];
#pragma unroll
            for (int i = 0; i < 8; i++)
#pragma unroll
                for (int j = 0; j < 8; j++)
                    acc[i][j] = fmaf(a[i], b[j], acc[i][j]);
        }
    }
#pragma unroll
    for (int i = 0; i < 8; i++) {
        float* Cp = C + (size_t)(m0 + ty * 8 + i) * N + n0 + tx * 8;
        *(float4*)Cp       = make_float4(acc[i][0], acc[i][1], acc[i][2], acc[i][3]);
        *(float4*)(Cp + 4) = make_float4(acc[i][4], acc[i][5], acc[i][6], acc[i][7]);
    }
}

// ----------------------------------------------------------------------------
// Flash-style causal attention, fp32.
// Block = (qb, h): 64 query rows of one head. 256 threads.
// Thread (ty = t/16, tx = t%16) owns S rows {ty+16k}, k=0..3 and, in the PV
// phase, O cols {tx+16k}, k=0..7. Online-softmax state (m, l) lives entirely
// in registers: each row is owned by exactly the 16 lanes sharing ty, which
// form a contiguous half-warp -> shfl_xor(8,4,2,1) reductions, no smem races.
// Smem: Qs[64][132], KV[64][132] (K then reused for V), Ss[64][68] (P^T).
// Strides 132/68 chosen so all compute-phase accesses are conflict-free or
// bounded 2-way.
// ----------------------------------------------------------------------------
#define QS_STRIDE 132
#define SS_STRIDE 68
#define ATT_SMEM_BYTES ((64 * QS_STRIDE * 2 + 64 * SS_STRIDE) * 4)

__global__ void __launch_bounds__(256) attn_kernel()
{
    extern __shared__ float sm[];
    float* Qs  = sm;                         // [64][132]
    float* KVs = sm + 64 * QS_STRIDE;        // [64][132]
    float* Ss  = sm + 2 * 64 * QS_STRIDE;    // [64][68], transposed [j][r]

    const int h   = blockIdx.y;
    const int qb  = blockIdx.x;
    const int kvh = h >> 2;                  // GQA: group = 4
    const int t   = threadIdx.x;
    const int tx  = t & 15;
    const int ty  = t >> 4;
    const float scale = 0.08838834764831845f; // 1/sqrt(128)

    // Load Q tile (pre-scaled)
    for (int e = t; e < 64 * 32; e += 256) {
        int rr = e >> 5, c4 = e & 31;
        float4 v = *(const float4*)&g_Q[(size_t)(qb * 64 + rr) * DIM + h * HD + (c4 << 2)];
        float* dst = &Qs[rr * QS_STRIDE + (c4 << 2)];
        dst[0] = v.x * scale; dst[1] = v.y * scale;
        dst[2] = v.z * scale; dst[3] = v.w * scale;
    }

    float m_run[4], l_run[4], acc[4][8];
#pragma unroll
    for (int ri = 0; ri < 4; ri++) {
        m_run[ri] = -INFINITY; l_run[ri] = 0.f;
#pragma unroll
        for (int ci = 0; ci < 8; ci++) acc[ri][ci] = 0.f;
    }
    __syncthreads();

    for (int kt = 0; kt <= qb; kt++) {
        // ---- load K tile ----
        for (int e = t; e < 64 * 32; e += 256) {
            int rr = e >> 5, c4 = e & 31;
            *(float4*)&KVs[rr * QS_STRIDE + (c4 << 2)] =
                *(const float4*)&g_K[(size_t)(kt * 64 + rr) * KVDIM + kvh * HD + (c4 << 2)];
        }
        __syncthreads();

        // ---- S = (Q*scale) K^T, 4x4 micro-tile, float4 over d ----
        float sv[4][4];
#pragma unroll
        for (int ri = 0; ri < 4; ri++)
#pragma unroll
            for (int ji = 0; ji < 4; ji++) sv[ri][ji] = 0.f;

        for (int d4 = 0; d4 < 32; d4++) {
            float4 q[4], k[4];
#pragma unroll
            for (int ri = 0; ri < 4; ri++)
                q[ri] = *(const float4*)&Qs[(ty + ri * 16) * QS_STRIDE + (d4 << 2)];
#pragma unroll
            for (int ji = 0; ji < 4; ji++)
                k[ji] = *(const float4*)&KVs[(tx + ji * 16) * QS_STRIDE + (d4 << 2)];
#pragma unroll
            for (int ri = 0; ri < 4; ri++)
#pragma unroll
                for (int ji = 0; ji < 4; ji++) {
                    sv[ri][ji] = fmaf(q[ri].x, k[ji].x, sv[ri][ji]);
                    sv[ri][ji] = fmaf(q[ri].y, k[ji].y, sv[ri][ji]);
                    sv[ri][ji] = fmaf(q[ri].z, k[ji].z, sv[ri][ji]);
                    sv[ri][ji] = fmaf(q[ri].w, k[ji].w, sv[ri][ji]);
                }
        }

        // ---- causal mask (diagonal tile only) ----
        if (kt == qb) {
#pragma unroll
            for (int ri = 0; ri < 4; ri++) {
                int row = ty + ri * 16;
#pragma unroll
                for (int ji = 0; ji < 4; ji++)
                    if (tx + ji * 16 > row) sv[ri][ji] = -INFINITY;
            }
        }

        // ---- online softmax (register state, half-warp shfl reductions) ----
#pragma unroll
        for (int ri = 0; ri < 4; ri++) {
            int row = ty + ri * 16;
            float mx = fmaxf(fmaxf(sv[ri][0], sv[ri][1]), fmaxf(sv[ri][2], sv[ri][3]));
#pragma unroll
            for (int o = 8; o >= 1; o >>= 1)
                mx = fmaxf(mx, __shfl_xor_sync(0xffffffffu, mx, o));
            float mn   = fmaxf(m_run[ri], mx);
            float corr = __expf(m_run[ri] - mn);
            m_run[ri]  = mn;
            float ls = 0.f;
#pragma unroll
            for (int ji = 0; ji < 4; ji++) {
                float e = __expf(sv[ri][ji] - mn);
                ls += e;
                Ss[(tx + ji * 16) * SS_STRIDE + row] = e;  // store P^T
            }
#pragma unroll
            for (int o = 8; o >= 1; o >>= 1)
                ls += __shfl_xor_sync(0xffffffffu, ls, o);
            l_run[ri] = l_run[ri] * corr + ls;
#pragma unroll
            for (int ci = 0; ci < 8; ci++) acc[ri][ci] *= corr;
        }
        __syncthreads();

        // ---- load V tile into the same buffer ----
        for (int e = t; e < 64 * 32; e += 256) {
            int rr = e >> 5, c4 = e & 31;
            *(float4*)&KVs[rr * QS_STRIDE + (c4 << 2)] =
                *(const float4*)&g_V[(size_t)(kt * 64 + rr) * KVDIM + kvh * HD + (c4 << 2)];
        }
        __syncthreads();

        // ---- O += P V : 4x8 micro-tile ----
        for (int j = 0; j < 64; j++) {
            float p[4], v[8];
#pragma unroll
            for (int ri = 0; ri < 4; ri++) p[ri] = Ss[j * SS_STRIDE + ty + ri * 16];
#pragma unroll
            for (int ci = 0; ci < 8; ci++) v[ci] = KVs[j * QS_STRIDE + tx + ci * 16];
#pragma unroll
            for (int ri = 0; ri < 4; ri++)
#pragma unroll
                for (int ci = 0; ci < 8; ci++)
                    acc[ri][ci] = fmaf(p[ri], v[ci], acc[ri][ci]);
        }
        __syncthreads();
    }

    // ---- normalize + write ----
#pragma unroll
    for (int ri = 0; ri < 4; ri++) {
        int row = ty + ri * 16;
        float inv = 1.f / l_run[ri];
        float* op = &g_attn[(size_t)(qb * 64 + row) * DIM + h * HD + tx];
#pragma unroll
        for (int ci = 0; ci < 8; ci++) op[ci * 16] = acc[ri][ci] * inv;
    }
}

// ----------------------------------------------------------------------------
// Launch
// ----------------------------------------------------------------------------
extern "C" void kernel_launch(void* const* d_in, const int* in_sizes, int n_in,
                              void* d_out, int out_size)
{
    const float* x  = (const float*)d_in[0];
    const float* wq = (const float*)d_in[1];
    const float* wk = (const float*)d_in[2];
    const float* wv = (const float*)d_in[3];
    const float* wo = (const float*)d_in[4];
    float* out = (float*)d_out;

    float *Q, *K, *V, *attn;
    cudaGetSymbolAddress((void**)&Q,    g_Q);
    cudaGetSymbolAddress((void**)&K,    g_K);
    cudaGetSymbolAddress((void**)&V,    g_V);
    cudaGetSymbolAddress((void**)&attn, g_attn);

    cudaFuncSetAttribute(attn_kernel,
                         cudaFuncAttributeMaxDynamicSharedMemorySize,
                         ATT_SMEM_BYTES);

    rope_table_kernel<<<SEQ * 64 / 256, 256>>>();

    gemm128<<<dim3(DIM   / 128, SEQ / 128), 256>>>(x, wq, Q, DIM,   DIM);
    gemm128<<<dim3(KVDIM / 128, SEQ / 128), 256>>>(x, wk, K, KVDIM, DIM);
    gemm128<<<dim3(KVDIM / 128, SEQ / 128), 256>>>(x, wv, V, KVDIM, DIM);

    rope_kernel<<<SEQ * NH  * 64 / 256, 256>>>(Q, NH,  DIM);
    rope_kernel<<<SEQ * NKV * 64 / 256, 256>>>(K, NKV, KVDIM);

    attn_kernel<<<dim3(SEQ / 64, NH), 256, ATT_SMEM_BYTES>>>();

    gemm128<<<dim3(DIM / 128, SEQ / 128), 256>>>(attn, wo, out, DIM, DIM);
}

// round 2
// speedup vs baseline: 2.1946x; 2.1946x over previous
#include <cuda_runtime.h>
#include <math.h>

// Problem constants
#define SEQ   2048
#define DIM   4096
#define NH    32
#define NKV   8
#define HD    128
#define KVDIM 1024   // NKV * HD

// ----------------------------------------------------------------------------
// Scratch (device-global: no allocations allowed anywhere)
// ----------------------------------------------------------------------------
__device__ float  g_Q[SEQ * DIM];      // 33.5 MB
__device__ float  g_K[SEQ * KVDIM];    //  8.4 MB
__device__ float  g_V[SEQ * KVDIM];    //  8.4 MB
__device__ float  g_attn[SEQ * DIM];   // 33.5 MB
__device__ float2 g_cs[SEQ * (HD / 2)];// rope cos/sin table

// ----------------------------------------------------------------------------
// RoPE cos/sin table (double-precision angles)
// ----------------------------------------------------------------------------
__global__ void __launch_bounds__(256) rope_table_kernel()
{
    int idx = blockIdx.x * blockDim.x + threadIdx.x;
    if (idx >= SEQ * 64) return;
    int s = idx >> 6, i = idx & 63;
    double freq = exp(-(double)i / 64.0 * log(500000.0));
    double a = (double)s * freq;
    g_cs[idx] = make_float2((float)cos(a), (float)sin(a));
}

// ----------------------------------------------------------------------------
// RoPE apply: pairs (2i, 2i+1) within each head
// ----------------------------------------------------------------------------
__global__ void __launch_bounds__(256) rope_kernel(float* __restrict__ X,
                                                   int nheads, int rowstride)
{
    int idx = blockIdx.x * blockDim.x + threadIdx.x;
    int i  = idx & 63;
    int hs = idx >> 6;
    int h  = hs % nheads;
    int s  = hs / nheads;
    float2 cs = g_cs[(s << 6) + i];
    float2* p = (float2*)(X + (size_t)s * rowstride + h * HD) + i;
    float2 v = *p;
    *p = make_float2(v.x * cs.x - v.y * cs.y,
                     v.x * cs.y + v.y * cs.x);
}

// ----------------------------------------------------------------------------
// tf32 tensor-core GEMM: C[M,N] = A[M,K] * B[N,K]^T (all row-major fp32).
// Block tile 128x128, BK=16, 256 threads = 8 warps in 2(m) x 4(n) layout,
// warp tile 64x32 = 4 m16 tiles x 4 n8 tiles, mma.sync.m16n8k8.tf32.
// Inputs rounded to tf32 with cvt.rna (round-to-nearest, no truncation bias).
// Smem stride 20 floats: fragment LDS pattern (20*q + c) mod 32 with
// q=lane/4 in 0..7, c=lane%4 in 0..3 hits 32 distinct banks -> conflict-free.
// ----------------------------------------------------------------------------
#define BK 16
#define SST 20   // smem row stride (floats)

__device__ __forceinline__ unsigned f2tf32(float x)
{
    unsigned r;
    asm("cvt.rna.tf32.f32 %0, %1;" : "=r"(r) : "f"(x));
    return r;
}

__device__ __forceinline__ void mma_tf32(float* c, const unsigned* a, const unsigned* b)
{
    asm volatile(
        "mma.sync.aligned.m16n8k8.row.col.f32.tf32.tf32.f32 "
        "{%0,%1,%2,%3}, {%4,%5,%6,%7}, {%8,%9}, {%0,%1,%2,%3};"
        : "+f"(c[0]), "+f"(c[1]), "+f"(c[2]), "+f"(c[3])
        : "r"(a[0]), "r"(a[1]), "r"(a[2]), "r"(a[3]),
          "r"(b[0]), "r"(b[1]));
}

__global__ void __launch_bounds__(256) gemm_tf32(const float* __restrict__ A,
                                                 const float* __restrict__ B,
                                                 float* __restrict__ C,
                                                 int N, int K)
{
    __shared__ unsigned As[128 * SST];
    __shared__ unsigned Bs[128 * SST];

    const int t    = threadIdx.x;
    const int lane = t & 31;
    const int wid  = t >> 5;
    const int wm   = wid & 1;   // 0..1 -> 64 rows each
    const int wn   = wid >> 1;  // 0..3 -> 32 cols each
    const int m0   = blockIdx.y << 7;
    const int n0   = blockIdx.x << 7;

    // Loader mapping: each thread owns 2 float4 per matrix per k-tile.
    // idx = t + 256*i : row = idx>>2 (0..127), kq = idx&3 (float4 within row)
    const int lrow0 = t >> 2, lkq0 = (t & 3) << 2;
    const int lrow1 = (t + 256) >> 2, lkq1 = ((t + 256) & 3) << 2;

    const float* Ag0 = A + (size_t)(m0 + lrow0) * K + lkq0;
    const float* Ag1 = A + (size_t)(m0 + lrow1) * K + lkq1;
    const float* Bg0 = B + (size_t)(n0 + lrow0) * K + lkq0;
    const float* Bg1 = B + (size_t)(n0 + lrow1) * K + lkq1;

    float acc[4][4][4];
#pragma unroll
    for (int mt = 0; mt < 4; mt++)
#pragma unroll
        for (int nt = 0; nt < 4; nt++)
#pragma unroll
            for (int r = 0; r < 4; r++) acc[mt][nt][r] = 0.f;

    // Prologue: fetch k-tile 0
    float4 va0 = *(const float4*)(Ag0);
    float4 va1 = *(const float4*)(Ag1);
    float4 vb0 = *(const float4*)(Bg0);
    float4 vb1 = *(const float4*)(Bg1);

    const int a_sts0 = lrow0 * SST + lkq0;
    const int a_sts1 = lrow1 * SST + lkq1;

    // Fragment base addresses (conflict-free per stride-20 analysis)
    const unsigned* Ap = As + ((wm << 6) + (lane >> 2)) * SST + (lane & 3);
    const unsigned* Bp = Bs + ((wn << 5) + (lane >> 2)) * SST + (lane & 3);

    const int ktiles = K / BK;
    for (int kt = 0; kt < ktiles; kt++) {
        __syncthreads();  // previous compute done before overwrite
        *(uint4*)&As[a_sts0] = make_uint4(f2tf32(va0.x), f2tf32(va0.y), f2tf32(va0.z), f2tf32(va0.w));
        *(uint4*)&As[a_sts1] = make_uint4(f2tf32(va1.x), f2tf32(va1.y), f2tf32(va1.z), f2tf32(va1.w));
        *(uint4*)&Bs[a_sts0] = make_uint4(f2tf32(vb0.x), f2tf32(vb0.y), f2tf32(vb0.z), f2tf32(vb0.w));
        *(uint4*)&Bs[a_sts1] = make_uint4(f2tf32(vb1.x), f2tf32(vb1.y), f2tf32(vb1.z), f2tf32(vb1.w));
        __syncthreads();

        if (kt + 1 < ktiles) {
            int ko = (kt + 1) * BK;
            va0 = *(const float4*)(Ag0 + ko);
            va1 = *(const float4*)(Ag1 + ko);
            vb0 = *(const float4*)(Bg0 + ko);
            vb1 = *(const float4*)(Bg1 + ko);
        }

#pragma unroll
        for (int c0 = 0; c0 < BK; c0 += 8) {
            unsigned af[4][4], bf[4][2];
#pragma unroll
            for (int mt = 0; mt < 4; mt++) {
                const unsigned* p = Ap + mt * (16 * SST) + c0;
                af[mt][0] = p[0];
                af[mt][1] = p[8 * SST];
                af[mt][2] = p[4];
                af[mt][3] = p[8 * SST + 4];
            }
#pragma unroll
            for (int nt = 0; nt < 4; nt++) {
                const unsigned* p = Bp + nt * (8 * SST) + c0;
                bf[nt][0] = p[0];
                bf[nt][1] = p[4];
            }
#pragma unroll
            for (int mt = 0; mt < 4; mt++)
#pragma unroll
                for (int nt = 0; nt < 4; nt++)
                    mma_tf32(acc[mt][nt], af[mt], bf[nt]);
        }
    }

    // Epilogue: c0,c1 -> (row, 2c),(row, 2c+1); c2,c3 -> row+8
    const int erow = m0 + (wm << 6) + (lane >> 2);
    const int ecol = n0 + (wn << 5) + ((lane & 3) << 1);
#pragma unroll
    for (int mt = 0; mt < 4; mt++) {
#pragma unroll
        for (int nt = 0; nt < 4; nt++) {
            float* p0 = C + (size_t)(erow + mt * 16) * N + ecol + nt * 8;
            float* p1 = p0 + 8 * N;
            *(float2*)p0 = make_float2(acc[mt][nt][0], acc[mt][nt][1]);
            *(float2*)p1 = make_float2(acc[mt][nt][2], acc[mt][nt][3]);
        }
    }
}

// ----------------------------------------------------------------------------
// Flash-style causal attention, fp32 (unchanged from round 1).
// ----------------------------------------------------------------------------
#define QS_STRIDE 132
#define SS_STRIDE 68
#define ATT_SMEM_BYTES ((64 * QS_STRIDE * 2 + 64 * SS_STRIDE) * 4)

__global__ void __launch_bounds__(256) attn_kernel()
{
    extern __shared__ float sm[];
    float* Qs  = sm;
    float* KVs = sm + 64 * QS_STRIDE;
    float* Ss  = sm + 2 * 64 * QS_STRIDE;

    const int h   = blockIdx.y;
    const int qb  = blockIdx.x;
    const int kvh = h >> 2;
    const int t   = threadIdx.x;
    const int tx  = t & 15;
    const int ty  = t >> 4;
    const float scale = 0.08838834764831845f;

    for (int e = t; e < 64 * 32; e += 256) {
        int rr = e >> 5, c4 = e & 31;
        float4 v = *(const float4*)&g_Q[(size_t)(qb * 64 + rr) * DIM + h * HD + (c4 << 2)];
        float* dst = &Qs[rr * QS_STRIDE + (c4 << 2)];
        dst[0] = v.x * scale; dst[1] = v.y * scale;
        dst[2] = v.z * scale; dst[3] = v.w * scale;
    }

    float m_run[4], l_run[4], acc[4][8];
#pragma unroll
    for (int ri = 0; ri < 4; ri++) {
        m_run[ri] = -INFINITY; l_run[ri] = 0.f;
#pragma unroll
        for (int ci = 0; ci < 8; ci++) acc[ri][ci] = 0.f;
    }
    __syncthreads();

    for (int kt = 0; kt <= qb; kt++) {
        for (int e = t; e < 64 * 32; e += 256) {
            int rr = e >> 5, c4 = e & 31;
            *(float4*)&KVs[rr * QS_STRIDE + (c4 << 2)] =
                *(const float4*)&g_K[(size_t)(kt * 64 + rr) * KVDIM + kvh * HD + (c4 << 2)];
        }
        __syncthreads();

        float sv[4][4];
#pragma unroll
        for (int ri = 0; ri < 4; ri++)
#pragma unroll
            for (int ji = 0; ji < 4; ji++) sv[ri][ji] = 0.f;

        for (int d4 = 0; d4 < 32; d4++) {
            float4 q[4], k[4];
#pragma unroll
            for (int ri = 0; ri < 4; ri++)
                q[ri] = *(const float4*)&Qs[(ty + ri * 16) * QS_STRIDE + (d4 << 2)];
#pragma unroll
            for (int ji = 0; ji < 4; ji++)
                k[ji] = *(const float4*)&KVs[(tx + ji * 16) * QS_STRIDE + (d4 << 2)];
#pragma unroll
            for (int ri = 0; ri < 4; ri++)
#pragma unroll
                for (int ji = 0; ji < 4; ji++) {
                    sv[ri][ji] = fmaf(q[ri].x, k[ji].x, sv[ri][ji]);
                    sv[ri][ji] = fmaf(q[ri].y, k[ji].y, sv[ri][ji]);
                    sv[ri][ji] = fmaf(q[ri].z, k[ji].z, sv[ri][ji]);
                    sv[ri][ji] = fmaf(q[ri].w, k[ji].w, sv[ri][ji]);
                }
        }

        if (kt == qb) {
#pragma unroll
            for (int ri = 0; ri < 4; ri++) {
                int row = ty + ri * 16;
#pragma unroll
                for (int ji = 0; ji < 4; ji++)
                    if (tx + ji * 16 > row) sv[ri][ji] = -INFINITY;
            }
        }

#pragma unroll
        for (int ri = 0; ri < 4; ri++) {
            int row = ty + ri * 16;
            float mx = fmaxf(fmaxf(sv[ri][0], sv[ri][1]), fmaxf(sv[ri][2], sv[ri][3]));
#pragma unroll
            for (int o = 8; o >= 1; o >>= 1)
                mx = fmaxf(mx, __shfl_xor_sync(0xffffffffu, mx, o));
            float mn   = fmaxf(m_run[ri], mx);
            float corr = __expf(m_run[ri] - mn);
            m_run[ri]  = mn;
            float ls = 0.f;
#pragma unroll
            for (int ji = 0; ji < 4; ji++) {
                float e = __expf(sv[ri][ji] - mn);
                ls += e;
                Ss[(tx + ji * 16) * SS_STRIDE + row] = e;
            }
#pragma unroll
            for (int o = 8; o >= 1; o >>= 1)
                ls += __shfl_xor_sync(0xffffffffu, ls, o);
            l_run[ri] = l_run[ri] * corr + ls;
#pragma unroll
            for (int ci = 0; ci < 8; ci++) acc[ri][ci] *= corr;
        }
        __syncthreads();

        for (int e = t; e < 64 * 32; e += 256) {
            int rr = e >> 5, c4 = e & 31;
            *(float4*)&KVs[rr * QS_STRIDE + (c4 << 2)] =
                *(const float4*)&g_V[(size_t)(kt * 64 + rr) * KVDIM + kvh * HD + (c4 << 2)];
        }
        __syncthreads();

        for (int j = 0; j < 64; j++) {
            float p[4], v[8];
#pragma unroll
            for (int ri = 0; ri < 4; ri++) p[ri] = Ss[j * SS_STRIDE + ty + ri * 16];
#pragma unroll
            for (int ci = 0; ci < 8; ci++) v[ci] = KVs[j * QS_STRIDE + tx + ci * 16];
#pragma unroll
            for (int ri = 0; ri < 4; ri++)
#pragma unroll
                for (int ci = 0; ci < 8; ci++)
                    acc[ri][ci] = fmaf(p[ri], v[ci], acc[ri][ci]);
        }
        __syncthreads();
    }

#pragma unroll
    for (int ri = 0; ri < 4; ri++) {
        int row = ty + ri * 16;
        float inv = 1.f / l_run[ri];
        float* op = &g_attn[(size_t)(qb * 64 + row) * DIM + h * HD + tx];
#pragma unroll
        for (int ci = 0; ci < 8; ci++) op[ci * 16] = acc[ri][ci] * inv;
    }
}

// ----------------------------------------------------------------------------
// Launch
// ----------------------------------------------------------------------------
extern "C" void kernel_launch(void* const* d_in, const int* in_sizes, int n_in,
                              void* d_out, int out_size)
{
    const float* x  = (const float*)d_in[0];
    const float* wq = (const float*)d_in[1];
    const float* wk = (const float*)d_in[2];
    const float* wv = (const float*)d_in[3];
    const float* wo = (const float*)d_in[4];
    float* out = (float*)d_out;

    float *Q, *K, *V, *attn;
    cudaGetSymbolAddress((void**)&Q,    g_Q);
    cudaGetSymbolAddress((void**)&K,    g_K);
    cudaGetSymbolAddress((void**)&V,    g_V);
    cudaGetSymbolAddress((void**)&attn, g_attn);

    cudaFuncSetAttribute(attn_kernel,
                         cudaFuncAttributeMaxDynamicSharedMemorySize,
                         ATT_SMEM_BYTES);

    rope_table_kernel<<<SEQ * 64 / 256, 256>>>();

    gemm_tf32<<<dim3(DIM   / 128, SEQ / 128), 256>>>(x, wq, Q, DIM,   DIM);
    gemm_tf32<<<dim3(KVDIM / 128, SEQ / 128), 256>>>(x, wk, K, KVDIM, DIM);
    gemm_tf32<<<dim3(KVDIM / 128, SEQ / 128), 256>>>(x, wv, V, KVDIM, DIM);

    rope_kernel<<<SEQ * NH  * 64 / 256, 256>>>(Q, NH,  DIM);
    rope_kernel<<<SEQ * NKV * 64 / 256, 256>>>(K, NKV, KVDIM);

    attn_kernel<<<dim3(SEQ / 64, NH), 256, ATT_SMEM_BYTES>>>();

    gemm_tf32<<<dim3(DIM / 128, SEQ / 128), 256>>>(attn, wo, out, DIM, DIM);
}